// round 3
// baseline (speedup 1.0000x reference)
#include <cuda_runtime.h>
#include <math.h>

#define HH 1024      // detector size / image size
#define AA 180       // number of angles
#define BB 16        // batch

// Filtered + angle-resampled sinogram: [b][a][h]
__device__ float g_xa[BB * AA * HH];
// Pre-scaled trig tables: g_cs[a] = 512*cos(theta_a), g_ns[a] = -512*sin(theta_a)
__device__ float g_cs[AA];
__device__ float g_ns[AA];

// ---------------------------------------------------------------------------
// Kernel 0: trig tables in double precision (immune to fast-math), once.
// ---------------------------------------------------------------------------
__global__ void init_tables_kernel() {
    int a = threadIdx.x;
    if (a < AA) {
        // match reference: t = float32(a) * float32(pi/180), trig at that point
        float tf = (float)a * 0.017453292519943295f;
        double t = (double)tf;
        g_cs[a] = (float)cos(t) * 512.0f;
        g_ns[a] = (float)(-sin(t)) * 512.0f;
    }
}

// ---------------------------------------------------------------------------
// Kernel 1: angle-resample + ramp filter (direct convolution == reference's
// padded-FFT filtering: padding to 2048 makes the circular conv wrap-free,
// and the symmetric kernel is 0.5 center, -2/(pi*d)^2 at odd d).
// One block per (angle, batch) column. 256 threads, 4 outputs each.
// ---------------------------------------------------------------------------
__global__ __launch_bounds__(256) void filter_kernel(const float* __restrict__ x) {
    const int a   = blockIdx.x;
    const int b   = blockIdx.y;
    const int tid = threadIdx.x;

    __shared__ float sh[3 * HH];      // [0,1024) zero | [1024,2048) data | [2048,3072) zero
    __shared__ float coef[HH / 2];    // coef[m] = -2 / (pi*(2m+1))^2

    for (int i = tid; i < HH; i += 256) {
        sh[i] = 0.0f;
        sh[2 * HH + i] = 0.0f;
    }
    for (int m = tid; m < HH / 2; m += 256) {
        float d  = 2.0f * (float)m + 1.0f;
        float pd = 3.14159265358979323846f * d;
        coef[m]  = -2.0f / (pd * pd);
    }

    // angle interpolation weights (xa resampling from reference; commutes
    // with the per-column linear filter)
    float ix = (float)a * (float)(180.0 / 179.0) - 0.5f;
    float fl = floorf(ix);
    int   i0 = (int)fl;
    float fx = ix - fl;
    int   i1 = i0 + 1;
    float w0 = (i0 >= 0 && i0 < AA) ? (1.0f - fx) : 0.0f;
    float w1 = (i1 >= 0 && i1 < AA) ? fx : 0.0f;
    int   c0 = min(max(i0, 0), AA - 1);
    int   c1 = min(max(i1, 0), AA - 1);

    const float* xb = x + (size_t)b * HH * AA;
    for (int k = tid; k < HH; k += 256) {
        sh[HH + k] = w0 * xb[k * AA + c0] + w1 * xb[k * AA + c1];
    }
    __syncthreads();

    const int h0 = tid;
    const int p0 = HH + h0;
    float acc0 = 0.5f * sh[p0];
    float acc1 = 0.5f * sh[p0 + 256];
    float acc2 = 0.5f * sh[p0 + 512];
    float acc3 = 0.5f * sh[p0 + 768];

    #pragma unroll 4
    for (int m = 0; m < HH / 2; m++) {
        int   d = 2 * m + 1;
        float c = coef[m];
        acc0 = fmaf(c, sh[p0 - d]       + sh[p0 + d],       acc0);
        acc1 = fmaf(c, sh[p0 + 256 - d] + sh[p0 + 256 + d], acc1);
        acc2 = fmaf(c, sh[p0 + 512 - d] + sh[p0 + 512 + d], acc2);
        acc3 = fmaf(c, sh[p0 + 768 - d] + sh[p0 + 768 + d], acc3);
    }

    float* out = g_xa + ((size_t)b * AA + a) * HH;
    out[h0]       = acc0;
    out[h0 + 256] = acc1;
    out[h0 + 512] = acc2;
    out[h0 + 768] = acc3;
}

// ---------------------------------------------------------------------------
// Kernel 2: backprojection. Block = 32x8 threads, each thread does 4 y-rows
// (32x32 pixel tile per block). Whole-warp outside-circle early out, now
// using the NEAREST point of each lane's 4-row strip (safe).
// ---------------------------------------------------------------------------
__global__ __launch_bounds__(256) void backproject_kernel(float* __restrict__ out) {
    __shared__ float s_cs[AA];
    __shared__ float s_ns[AA];

    const int tid = threadIdx.y * 32 + threadIdx.x;
    if (tid < AA) {
        s_cs[tid] = g_cs[tid];
        s_ns[tid] = g_ns[tid];
    }
    __syncthreads();

    const int b     = blockIdx.z;
    const int px    = blockIdx.x * 32 + threadIdx.x;
    const int ybase = blockIdx.y * 32 + threadIdx.y * 4;

    const float step = 2.0f / 1023.0f;
    const float ux  = fmaf((float)px, step, -1.0f);
    float uy[4];
    #pragma unroll
    for (int i = 0; i < 4; i++) uy[i] = fmaf((float)(ybase + i), step, -1.0f);

    // Early out only if even the NEAREST pixel of every lane's strip is
    // outside the unit circle.
    float uy2min = (uy[0] * uy[3] <= 0.0f)
                 ? 0.0f
                 : fminf(uy[0] * uy[0], uy[3] * uy[3]);
    bool allout = __all_sync(0xFFFFFFFFu, ux * ux + uy2min > 1.0f);

    float acc[4] = {0.0f, 0.0f, 0.0f, 0.0f};

    if (!allout) {
        const float* __restrict__ xab = g_xa + (size_t)b * AA * HH;
        for (int a = 0; a < AA; a++) {
            const float cs = s_cs[a];      //  512*cos
            const float ns = s_ns[a];      // -512*sin
            const float* __restrict__ v = xab + a * HH;
            const float base = fmaf(ux, cs, 511.5f);   // iy = 512*T + 511.5
            #pragma unroll
            for (int i = 0; i < 4; i++) {
                float iy = fmaf(uy[i], ns, base);
                float fl = floorf(iy);
                int   j0 = (int)fl;
                float fy = iy - fl;
                bool  in0 = (unsigned)j0 < (unsigned)HH;
                bool  in1 = (unsigned)(j0 + 1) < (unsigned)HH;
                float w0 = in0 ? (1.0f - fy) : 0.0f;
                float w1 = in1 ? fy : 0.0f;
                int j0c = min(max(j0, 0), HH - 1);
                int j1c = min(max(j0 + 1, 0), HH - 1);
                float v0 = __ldg(v + j0c);
                float v1 = __ldg(v + j1c);
                acc[i] = fmaf(v0, w0, acc[i]);
                acc[i] = fmaf(v1, w1, acc[i]);
            }
        }
    }

    const float scale = (float)(3.14159265358979323846 / 360.0);  // pi / (2*A)
    float* ob = out + (size_t)b * HH * HH;
    #pragma unroll
    for (int i = 0; i < 4; i++) {
        float r2 = fmaf(uy[i], uy[i], ux * ux);
        float val = (r2 <= 1.0f) ? acc[i] * scale : 0.0f;
        ob[(size_t)(ybase + i) * HH + px] = val;
    }
}

// ---------------------------------------------------------------------------
extern "C" void kernel_launch(void* const* d_in, const int* in_sizes, int n_in,
                              void* d_out, int out_size) {
    const float* x = (const float*)d_in[0];
    float* out = (float*)d_out;

    init_tables_kernel<<<1, 192>>>();
    filter_kernel<<<dim3(AA, BB), 256>>>(x);
    backproject_kernel<<<dim3(HH / 32, HH / 32, BB), dim3(32, 8)>>>(out);
}

// round 4
// speedup vs baseline: 2.5274x; 2.5274x over previous
#include <cuda_runtime.h>
#include <math.h>

#define HH 1024      // detector size / image size
#define AA 180       // number of angles
#define BB 16        // batch

#define ROWPAD 1028  // float2 entries per padded sinogram row (valid 0..1025)

// Padded float2 sinogram: p2[i] = (v[i-1], v[i]), with v[-1]=v[1024]=0.
// Lookup for bilinear pair (v[j0], v[j0+1]) is p2[j0+1].
__device__ float2 g_xa2[BB * AA * ROWPAD];
// Pre-scaled trig tables: g_cs[a] = 512*cos(theta_a), g_ns[a] = -512*sin(theta_a)
__device__ float g_cs[AA];
__device__ float g_ns[AA];

// ---------------------------------------------------------------------------
// Kernel 1: angle-resample + ramp filter (direct convolution == reference's
// padded-FFT filtering, which is wrap-free). Writes the padded float2 layout.
// Blocks with b==0 also fill the trig tables (double precision).
// One block per (angle, batch) column. 256 threads, 4 outputs each.
// ---------------------------------------------------------------------------
__global__ __launch_bounds__(256) void filter_kernel(const float* __restrict__ x) {
    const int a   = blockIdx.x;
    const int b   = blockIdx.y;
    const int tid = threadIdx.x;

    // trig tables (once, by the b==0 blocks; backproject launches after us)
    if (b == 0 && tid == 0) {
        float tf = (float)a * 0.017453292519943295f;   // match reference f32 angle
        double t = (double)tf;
        g_cs[a] = (float)cos(t) * 512.0f;
        g_ns[a] = (float)(-sin(t)) * 512.0f;
    }

    __shared__ float sh[3 * HH];      // [0,1024) zero | [1024,2048) data | [2048,3072) zero
    __shared__ float coef[HH / 2];    // coef[m] = -2 / (pi*(2m+1))^2

    for (int i = tid; i < HH; i += 256) {
        sh[i] = 0.0f;
        sh[2 * HH + i] = 0.0f;
    }
    for (int m = tid; m < HH / 2; m += 256) {
        float d  = 2.0f * (float)m + 1.0f;
        float pd = 3.14159265358979323846f * d;
        coef[m]  = -2.0f / (pd * pd);
    }

    // angle interpolation weights (xa resampling; commutes with linear filter)
    float ix = (float)a * (float)(180.0 / 179.0) - 0.5f;
    float fl = floorf(ix);
    int   i0 = (int)fl;
    float fx = ix - fl;
    int   i1 = i0 + 1;
    float w0 = (i0 >= 0 && i0 < AA) ? (1.0f - fx) : 0.0f;
    float w1 = (i1 >= 0 && i1 < AA) ? fx : 0.0f;
    int   c0 = min(max(i0, 0), AA - 1);
    int   c1 = min(max(i1, 0), AA - 1);

    const float* xb = x + (size_t)b * HH * AA;
    for (int k = tid; k < HH; k += 256) {
        sh[HH + k] = w0 * xb[k * AA + c0] + w1 * xb[k * AA + c1];
    }
    __syncthreads();

    const int h0 = tid;
    const int p0 = HH + h0;
    float acc0 = 0.5f * sh[p0];
    float acc1 = 0.5f * sh[p0 + 256];
    float acc2 = 0.5f * sh[p0 + 512];
    float acc3 = 0.5f * sh[p0 + 768];

    #pragma unroll 8
    for (int m = 0; m < HH / 2; m++) {
        int   d = 2 * m + 1;
        float c = coef[m];
        acc0 = fmaf(c, sh[p0 - d]       + sh[p0 + d],       acc0);
        acc1 = fmaf(c, sh[p0 + 256 - d] + sh[p0 + 256 + d], acc1);
        acc2 = fmaf(c, sh[p0 + 512 - d] + sh[p0 + 512 + d], acc2);
        acc3 = fmaf(c, sh[p0 + 768 - d] + sh[p0 + 768 + d], acc3);
    }

    // Store into padded float2 layout: p2[h+1].x = v[h], p2[h].y = v[h]
    float* row = (float*)(g_xa2 + ((size_t)b * AA + a) * ROWPAD);
    float accs[4] = {acc0, acc1, acc2, acc3};
    #pragma unroll
    for (int i = 0; i < 4; i++) {
        int h = h0 + i * 256;
        row[(h + 1) * 2]     = accs[i];   // p2[h+1].x
        row[h * 2 + 1]       = accs[i];   // p2[h].y
    }
    if (tid == 0) {
        row[0]            = 0.0f;   // p2[0].x      = v[-1]
        row[1024 * 2 + 1] = 0.0f;   // p2[1024].y   = v[1024]
        row[1025 * 2]     = 0.0f;   // p2[1025]     = (0,0)  (clamp target)
        row[1025 * 2 + 1] = 0.0f;
    }
}

// ---------------------------------------------------------------------------
// Kernel 2: backprojection with shared-memory window staging.
// Block = 32x8 threads = 32x32 pixel tile (4 y-rows per thread).
// Per angle, the tile's detector footprint is a contiguous window of
// <=44 elements; windows for CH angles are staged in smem as float2 pairs.
// ---------------------------------------------------------------------------
#define CH  20                 // angles per chunk (180 = 9 * 20)
#define NCH (AA / CH)
#define WIN 48                 // window entries per angle (covers 44 + guards)

__global__ __launch_bounds__(256) void backproject_kernel(float* __restrict__ out) {
    __shared__ float4 s_meta[AA];          // cs, ns, off = 511.5 - jminf, unused
    __shared__ int    s_jmin[AA];
    __shared__ float2 s_win[CH * WIN];

    const int tid = threadIdx.y * 32 + threadIdx.x;
    const int b   = blockIdx.z;
    const int x0  = blockIdx.x * 32;
    const int y0  = blockIdx.y * 32;

    const float step = 2.0f / 1023.0f;
    const float ux_lo = fmaf((float)x0,        step, -1.0f);
    const float ux_hi = fmaf((float)(x0 + 31), step, -1.0f);
    const float uy_lo = fmaf((float)y0,        step, -1.0f);
    const float uy_hi = fmaf((float)(y0 + 31), step, -1.0f);

    const int px    = x0 + threadIdx.x;
    const int ybase = y0 + threadIdx.y * 4;
    float* ob = out + (size_t)b * HH * HH;

    const float ux = fmaf((float)px, step, -1.0f);
    float uy[4];
    #pragma unroll
    for (int i = 0; i < 4; i++) uy[i] = fmaf((float)(ybase + i), step, -1.0f);

    // Block-level skip: nearest point of the whole tile outside unit circle.
    {
        float nx = (ux_lo > 0.0f) ? ux_lo : ((ux_hi < 0.0f) ? ux_hi : 0.0f);
        float ny = (uy_lo > 0.0f) ? uy_lo : ((uy_hi < 0.0f) ? uy_hi : 0.0f);
        if (nx * nx + ny * ny > 1.0f) {
            #pragma unroll
            for (int i = 0; i < 4; i++)
                ob[(size_t)(ybase + i) * HH + px] = 0.0f;
            return;
        }
    }

    // Per-angle metadata: window start (from tile-corner extremes; linear in
    // x,y so corners bound everything, with -1 floor guard).
    if (tid < AA) {
        float cs = g_cs[tid];
        float ns = g_ns[tid];
        float mn = fminf(ux_lo * cs, ux_hi * cs)
                 + fminf(uy_lo * ns, uy_hi * ns) + 511.5f;
        float jminf = floorf(mn) - 1.0f;
        s_meta[tid] = make_float4(cs, ns, 511.5f - jminf, 0.0f);
        s_jmin[tid] = (int)jminf;
    }

    // Warp early-out using NEAREST pixel of each lane's 4-row strip.
    float uy2min = (uy[0] * uy[3] <= 0.0f)
                 ? 0.0f
                 : fminf(uy[0] * uy[0], uy[3] * uy[3]);
    const bool active = !__all_sync(0xFFFFFFFFu, ux * ux + uy2min > 1.0f);

    float acc[4] = {0.0f, 0.0f, 0.0f, 0.0f};
    const float2* __restrict__ rowb = g_xa2 + (size_t)b * AA * ROWPAD;

    for (int ch = 0; ch < NCH; ch++) {
        const int abase = ch * CH;
        __syncthreads();   // meta ready (first iter) / previous chunk consumed
        // Cooperative window load: CH*WIN float2 per chunk.
        #pragma unroll
        for (int idx = tid; idx < CH * WIN; idx += 256) {
            int slot = idx / WIN;
            int k    = idx - slot * WIN;
            int a    = abase + slot;
            int src  = s_jmin[a] + 1 + k;
            src = min(max(src, 0), 1025);
            s_win[idx] = rowb[(size_t)a * ROWPAD + src];
        }
        __syncthreads();

        if (active) {
            #pragma unroll 2
            for (int slot = 0; slot < CH; slot++) {
                float4 m = s_meta[abase + slot];
                float base = fmaf(ux, m.x, m.z);       // window-relative coord
                const float2* w = s_win + slot * WIN;
                #pragma unroll
                for (int i = 0; i < 4; i++) {
                    float kf = fmaf(uy[i], m.y, base);
                    float fl = floorf(kf);
                    float fy = kf - fl;
                    int   k  = (int)fl;
                    k = min(max(k, 0), WIN - 1);       // only outside pixels clamp
                    float2 v = w[k];
                    float  d = v.y - v.x;
                    acc[i] += v.x;
                    acc[i] = fmaf(fy, d, acc[i]);
                }
            }
        }
    }

    const float scale = (float)(3.14159265358979323846 / 360.0);  // pi / (2*A)
    #pragma unroll
    for (int i = 0; i < 4; i++) {
        float r2  = fmaf(uy[i], uy[i], ux * ux);
        float val = (r2 <= 1.0f) ? acc[i] * scale : 0.0f;
        ob[(size_t)(ybase + i) * HH + px] = val;
    }
}

// ---------------------------------------------------------------------------
extern "C" void kernel_launch(void* const* d_in, const int* in_sizes, int n_in,
                              void* d_out, int out_size) {
    const float* x = (const float*)d_in[0];
    float* out = (float*)d_out;

    filter_kernel<<<dim3(AA, BB), 256>>>(x);
    backproject_kernel<<<dim3(HH / 32, HH / 32, BB), dim3(32, 8)>>>(out);
}

// round 5
// speedup vs baseline: 3.4220x; 1.3540x over previous
#include <cuda_runtime.h>
#include <math.h>

#define HH 1024      // detector size / image size
#define AA 180       // number of angles
#define BB 16        // batch

#define ROWPAD 1028  // float2 entries per padded sinogram row (valid 0..1025)

// Padded float2 sinogram: p2[i] = (v[i-1], v[i]), with v[-1]=v[1024]=0.
// Lookup for bilinear pair (v[j0], v[j0+1]) is p2[j0+1].
__device__ float2 g_xa2[BB * AA * ROWPAD];
// Pre-scaled trig tables: g_cs[a] = 512*cos(theta_a), g_ns[a] = -512*sin(theta_a)
__device__ float g_cs[AA];
__device__ float g_ns[AA];

// ---------------------------------------------------------------------------
// Kernel 1: angle-resample + ramp filter (direct convolution == reference's
// padded-FFT filtering, which is wrap-free). Writes the padded float2 layout.
// Blocks with b==0 also fill the trig tables (double precision).
// One block per (angle, batch) column. 256 threads, 4 outputs each.
// ---------------------------------------------------------------------------
__global__ __launch_bounds__(256) void filter_kernel(const float* __restrict__ x) {
    const int a   = blockIdx.x;
    const int b   = blockIdx.y;
    const int tid = threadIdx.x;

    if (b == 0 && tid == 0) {
        float tf = (float)a * 0.017453292519943295f;   // match reference f32 angle
        double t = (double)tf;
        g_cs[a] = (float)cos(t) * 512.0f;
        g_ns[a] = (float)(-sin(t)) * 512.0f;
    }

    __shared__ float sh[3 * HH];      // [0,1024) zero | [1024,2048) data | [2048,3072) zero
    __shared__ float coef[HH / 2];    // coef[m] = -2 / (pi*(2m+1))^2

    for (int i = tid; i < HH; i += 256) {
        sh[i] = 0.0f;
        sh[2 * HH + i] = 0.0f;
    }
    for (int m = tid; m < HH / 2; m += 256) {
        float d  = 2.0f * (float)m + 1.0f;
        float pd = 3.14159265358979323846f * d;
        coef[m]  = -2.0f / (pd * pd);
    }

    // angle interpolation weights (xa resampling; commutes with linear filter)
    float ix = (float)a * (float)(180.0 / 179.0) - 0.5f;
    float fl = floorf(ix);
    int   i0 = (int)fl;
    float fx = ix - fl;
    int   i1 = i0 + 1;
    float w0 = (i0 >= 0 && i0 < AA) ? (1.0f - fx) : 0.0f;
    float w1 = (i1 >= 0 && i1 < AA) ? fx : 0.0f;
    int   c0 = min(max(i0, 0), AA - 1);
    int   c1 = min(max(i1, 0), AA - 1);

    const float* xb = x + (size_t)b * HH * AA;
    for (int k = tid; k < HH; k += 256) {
        sh[HH + k] = w0 * xb[k * AA + c0] + w1 * xb[k * AA + c1];
    }
    __syncthreads();

    const int h0 = tid;
    const int p0 = HH + h0;
    float acc0 = 0.5f * sh[p0];
    float acc1 = 0.5f * sh[p0 + 256];
    float acc2 = 0.5f * sh[p0 + 512];
    float acc3 = 0.5f * sh[p0 + 768];

    #pragma unroll 8
    for (int m = 0; m < HH / 2; m++) {
        int   d = 2 * m + 1;
        float c = coef[m];
        acc0 = fmaf(c, sh[p0 - d]       + sh[p0 + d],       acc0);
        acc1 = fmaf(c, sh[p0 + 256 - d] + sh[p0 + 256 + d], acc1);
        acc2 = fmaf(c, sh[p0 + 512 - d] + sh[p0 + 512 + d], acc2);
        acc3 = fmaf(c, sh[p0 + 768 - d] + sh[p0 + 768 + d], acc3);
    }

    // Store into padded float2 layout: p2[h+1].x = v[h], p2[h].y = v[h]
    float* row = (float*)(g_xa2 + ((size_t)b * AA + a) * ROWPAD);
    float accs[4] = {acc0, acc1, acc2, acc3};
    #pragma unroll
    for (int i = 0; i < 4; i++) {
        int h = h0 + i * 256;
        row[(h + 1) * 2] = accs[i];   // p2[h+1].x
        row[h * 2 + 1]   = accs[i];   // p2[h].y
    }
    if (tid == 0) {
        row[0]            = 0.0f;   // p2[0].x    = v[-1]
        row[1024 * 2 + 1] = 0.0f;   // p2[1024].y = v[1024]
        row[1025 * 2]     = 0.0f;   // p2[1025]   = (0,0) (edge-fetch target)
        row[1025 * 2 + 1] = 0.0f;
    }
}

// ---------------------------------------------------------------------------
// Kernel 2: backprojection with shared-memory window staging.
// Block = 32x8 threads = 32x32 pixel tile (4 y-rows per thread).
// Per angle, the tile's detector footprint is a contiguous window of
// <=44 elements (tile extent 31.03*(|cos|+|sin|) <= 43.9); windows for CH
// angles are staged in smem as (value, diff) pairs. Window bounds come from
// tile-corner extremes, so EVERY in-tile pixel maps to k in [0,45] -- no
// per-sample clamp needed.
// ---------------------------------------------------------------------------
#define CH  20                 // angles per chunk (180 = 9 * 20)
#define NCH (AA / CH)
#define WIN 48                 // window entries per angle (44 + guards)

__global__ __launch_bounds__(256) void backproject_kernel(float* __restrict__ out) {
    __shared__ float4 s_meta[AA];          // cs, ns, off(=511.5-jminf+slot*WIN), 0
    __shared__ int    s_jmin[AA];
    __shared__ float2 s_win[CH * WIN];

    const int tid = threadIdx.y * 32 + threadIdx.x;
    const int b   = blockIdx.z;
    const int x0  = blockIdx.x * 32;
    const int y0  = blockIdx.y * 32;

    const float step = 2.0f / 1023.0f;
    const float ux_lo = fmaf((float)x0,        step, -1.0f);
    const float ux_hi = fmaf((float)(x0 + 31), step, -1.0f);
    const float uy_lo = fmaf((float)y0,        step, -1.0f);
    const float uy_hi = fmaf((float)(y0 + 31), step, -1.0f);

    const int px    = x0 + threadIdx.x;
    const int ybase = y0 + threadIdx.y * 4;
    float* ob = out + (size_t)b * HH * HH;

    const float ux = fmaf((float)px, step, -1.0f);
    float uy[4];
    #pragma unroll
    for (int i = 0; i < 4; i++) uy[i] = fmaf((float)(ybase + i), step, -1.0f);

    // Block-level skip: nearest point of the whole tile outside unit circle.
    {
        float nx = (ux_lo > 0.0f) ? ux_lo : ((ux_hi < 0.0f) ? ux_hi : 0.0f);
        float ny = (uy_lo > 0.0f) ? uy_lo : ((uy_hi < 0.0f) ? uy_hi : 0.0f);
        if (nx * nx + ny * ny > 1.0f) {
            #pragma unroll
            for (int i = 0; i < 4; i++)
                ob[(size_t)(ybase + i) * HH + px] = 0.0f;
            return;
        }
    }

    // Per-angle metadata: window start from tile-corner extremes (linear in
    // x,y so corners bound everything), -1 floor guard. Offset also folds in
    // the angle's smem window slot (slot*WIN) so k indexes s_win directly.
    if (tid < AA) {
        float cs = g_cs[tid];
        float ns = g_ns[tid];
        float mn = fminf(ux_lo * cs, ux_hi * cs)
                 + fminf(uy_lo * ns, uy_hi * ns) + 511.5f;
        float jminf = floorf(mn) - 1.0f;
        float off   = 511.5f - jminf + (float)((tid % CH) * WIN);
        s_meta[tid] = make_float4(cs, ns, off, 0.0f);
        s_jmin[tid] = (int)jminf;
    }

    // Warp early-out using NEAREST pixel of each lane's 4-row strip.
    float uy2min = (uy[0] * uy[3] <= 0.0f)
                 ? 0.0f
                 : fminf(uy[0] * uy[0], uy[3] * uy[3]);
    const bool active = !__all_sync(0xFFFFFFFFu, ux * ux + uy2min > 1.0f);

    float acc[4] = {0.0f, 0.0f, 0.0f, 0.0f};
    const float2* __restrict__ rowb = g_xa2 + (size_t)b * AA * ROWPAD;

    for (int ch = 0; ch < NCH; ch++) {
        const int abase = ch * CH;
        __syncthreads();   // meta ready (first iter) / previous chunk consumed
        // Cooperative window load; store (value, diff) pairs.
        #pragma unroll
        for (int idx = tid; idx < CH * WIN; idx += 256) {
            int slot = idx / WIN;
            int k    = idx - slot * WIN;
            int a    = abase + slot;
            int src  = s_jmin[a] + 1 + k;
            src = min(max(src, 0), 1025);
            float2 v = rowb[(size_t)a * ROWPAD + src];
            s_win[idx] = make_float2(v.x, v.y - v.x);
        }
        __syncthreads();

        if (active) {
            #pragma unroll 4
            for (int slot = 0; slot < CH; slot++) {
                float4 m = s_meta[abase + slot];
                float base = fmaf(ux, m.x, m.z);     // window coord incl. slot
                #pragma unroll
                for (int i = 0; i < 4; i++) {
                    float kf = fmaf(uy[i], m.y, base);
                    int   k  = __float2int_rd(kf);     // k in [0, WIN*CH): no clamp
                    float fy = kf - (float)k;
                    float2 w = s_win[k];
                    acc[i] += w.x;
                    acc[i] = fmaf(fy, w.y, acc[i]);
                }
            }
        }
    }

    const float scale = (float)(3.14159265358979323846 / 360.0);  // pi / (2*A)
    #pragma unroll
    for (int i = 0; i < 4; i++) {
        float r2  = fmaf(uy[i], uy[i], ux * ux);
        float val = (r2 <= 1.0f) ? acc[i] * scale : 0.0f;
        ob[(size_t)(ybase + i) * HH + px] = val;
    }
}

// ---------------------------------------------------------------------------
extern "C" void kernel_launch(void* const* d_in, const int* in_sizes, int n_in,
                              void* d_out, int out_size) {
    const float* x = (const float*)d_in[0];
    float* out = (float*)d_out;

    filter_kernel<<<dim3(AA, BB), 256>>>(x);
    backproject_kernel<<<dim3(HH / 32, HH / 32, BB), dim3(32, 8)>>>(out);
}

// round 6
// speedup vs baseline: 5.7327x; 1.6752x over previous
#include <cuda_runtime.h>
#include <cuda_fp16.h>
#include <math.h>

#define HH 1024      // detector size / image size
#define AA 180       // number of angles
#define BB 16        // batch
#define NBP (BB / 2) // batch pairs

#define ROWP 1028    // half2 entries per padded row (valid src 0..1025)
#define MTAP 128     // filter taps: m < MTAP, i.e. |d| <= 255 (tail ~5e-5 rel)

// Window value/diff planes, one half per batch of the pair:
//   g_wv[bp][a][j] = half2( v_b0[j-1], v_b1[j-1] )
//   g_wd[bp][a][j] = half2( v_b0[j]-v_b0[j-1], v_b1[j]-v_b1[j-1] )
// with v[-1] = v[1024] = 0. Bilinear pair (v[j0], v[j0+1]) lives at j = j0+1.
__device__ __half2 g_wv[NBP * AA * ROWP];
__device__ __half2 g_wd[NBP * AA * ROWP];
// Pre-scaled trig: g_cs[a] = 512*cos(theta_a), g_ns[a] = -512*sin(theta_a)
__device__ float g_cs[AA];
__device__ float g_ns[AA];

// ---------------------------------------------------------------------------
// Kernel 1: angle-resample + truncated ramp-filter convolution (equivalent to
// the reference's wrap-free padded-FFT filtering; taps beyond |d|=255 dropped,
// tail contribution ~5e-5 relative). Writes fp16 (value,diff) planes.
// One block per (angle, batch) column. 256 threads, 4 outputs each.
// ---------------------------------------------------------------------------
__global__ __launch_bounds__(256) void filter_kernel(const float* __restrict__ x) {
    const int a   = blockIdx.x;
    const int b   = blockIdx.y;
    const int tid = threadIdx.x;

    if (b == 0 && tid == 0) {
        float tf = (float)a * 0.017453292519943295f;   // reference f32 angle
        double t = (double)tf;
        g_cs[a] = (float)cos(t) * 512.0f;
        g_ns[a] = (float)(-sin(t)) * 512.0f;
    }

    __shared__ float sh[3 * HH];   // [0,1024) pad/reuse | [1024,2048) data | [2048,3072) pad
    __shared__ float coef[MTAP];   // coef[m] = -2 / (pi*(2m+1))^2

    for (int i = tid; i < HH; i += 256) {
        sh[i] = 0.0f;
        sh[2 * HH + i] = 0.0f;
    }
    if (tid < MTAP) {
        float d  = 2.0f * (float)tid + 1.0f;
        float pd = 3.14159265358979323846f * d;
        coef[tid] = -2.0f / (pd * pd);
    }

    // angle interpolation weights (commute with the linear filter)
    float ix = (float)a * (float)(180.0 / 179.0) - 0.5f;
    float fl = floorf(ix);
    int   i0 = (int)fl;
    float fx = ix - fl;
    int   i1 = i0 + 1;
    float w0 = (i0 >= 0 && i0 < AA) ? (1.0f - fx) : 0.0f;
    float w1 = (i1 >= 0 && i1 < AA) ? fx : 0.0f;
    int   c0 = min(max(i0, 0), AA - 1);
    int   c1 = min(max(i1, 0), AA - 1);

    const float* xb = x + (size_t)b * HH * AA;
    for (int k = tid; k < HH; k += 256) {
        sh[HH + k] = w0 * xb[k * AA + c0] + w1 * xb[k * AA + c1];
    }
    __syncthreads();

    const int h0 = tid;
    const int p0 = HH + h0;
    float acc0 = 0.5f * sh[p0];
    float acc1 = 0.5f * sh[p0 + 256];
    float acc2 = 0.5f * sh[p0 + 512];
    float acc3 = 0.5f * sh[p0 + 768];

    #pragma unroll 8
    for (int m = 0; m < MTAP; m++) {
        int   d = 2 * m + 1;
        float c = coef[m];
        acc0 = fmaf(c, sh[p0 - d]       + sh[p0 + d],       acc0);
        acc1 = fmaf(c, sh[p0 + 256 - d] + sh[p0 + 256 + d], acc1);
        acc2 = fmaf(c, sh[p0 + 512 - d] + sh[p0 + 512 + d], acc2);
        acc3 = fmaf(c, sh[p0 + 768 - d] + sh[p0 + 768 + d], acc3);
    }
    __syncthreads();                 // done reading sh before reuse

    // stash filtered column v[0..1023] into sh[0..1024)
    sh[h0]       = acc0;
    sh[h0 + 256] = acc1;
    sh[h0 + 512] = acc2;
    sh[h0 + 768] = acc3;
    __syncthreads();

    const size_t rowoff = ((size_t)(b >> 1) * AA + a) * ROWP;
    __half* wv = (__half*)(g_wv + rowoff);
    __half* wd = (__half*)(g_wd + rowoff);
    const int sub = b & 1;

    #pragma unroll
    for (int i = 0; i < 4; i++) {
        int   h  = h0 + i * 256;
        float vh = sh[h];
        float vp = (h > 0) ? sh[h - 1] : 0.0f;
        wv[2 * (h + 1) + sub] = __float2half_rn(vh);       // wv[j=h+1] = v[h]
        wd[2 * h + sub]       = __float2half_rn(vh - vp);  // wd[j=h]   = v[h]-v[h-1]
    }
    if (tid == 0) {
        wv[sub]              = __float2half_rn(0.0f);          // wv[0] = v[-1] = 0
        wd[2 * 1024 + sub]   = __float2half_rn(-sh[1023]);     // v[1024]-v[1023]
        wv[2 * 1025 + sub]   = __float2half_rn(0.0f);          // wv[1025] = v[1024] = 0
        wd[2 * 1025 + sub]   = __float2half_rn(0.0f);
    }
}

// ---------------------------------------------------------------------------
// Kernel 2: backprojection, 2 batches per block (shared geometry), fp16
// (value,diff) window staging. Block = 32x8 = 32x32 pixel tile, 4 y-rows and
// 2 batches per thread. Window bounds from tile-corner extremes -> every
// in-tile sample maps to k in [0, WIN-2]; no per-sample clamp.
// ---------------------------------------------------------------------------
#define CH  20                 // angles per chunk (180 = 9 * 20)
#define NCH (AA / CH)
#define WIN 48                 // window entries per angle (44 span + guards)

__global__ __launch_bounds__(256) void backproject_kernel(float* __restrict__ out) {
    __shared__ float4  s_meta[AA];          // cs, ns, off(=511.5-jminf+slot*WIN), 0
    __shared__ int     s_jmin[AA];
    __shared__ __half2 s_w[2 * CH * WIN];   // [0,960) values | [960,1920) diffs

    const int tid = threadIdx.y * 32 + threadIdx.x;
    const int bp  = blockIdx.z;
    const int x0  = blockIdx.x * 32;
    const int y0  = blockIdx.y * 32;

    const float step = 2.0f / 1023.0f;
    const float ux_lo = fmaf((float)x0,        step, -1.0f);
    const float ux_hi = fmaf((float)(x0 + 31), step, -1.0f);
    const float uy_lo = fmaf((float)y0,        step, -1.0f);
    const float uy_hi = fmaf((float)(y0 + 31), step, -1.0f);

    const int px    = x0 + threadIdx.x;
    const int ybase = y0 + threadIdx.y * 4;
    float* obA = out + (size_t)(2 * bp) * HH * HH;
    float* obB = obA + (size_t)HH * HH;

    const float ux = fmaf((float)px, step, -1.0f);
    float uy[4];
    #pragma unroll
    for (int i = 0; i < 4; i++) uy[i] = fmaf((float)(ybase + i), step, -1.0f);

    // Block-level skip: nearest tile point outside unit circle.
    {
        float nx = (ux_lo > 0.0f) ? ux_lo : ((ux_hi < 0.0f) ? ux_hi : 0.0f);
        float ny = (uy_lo > 0.0f) ? uy_lo : ((uy_hi < 0.0f) ? uy_hi : 0.0f);
        if (nx * nx + ny * ny > 1.0f) {
            #pragma unroll
            for (int i = 0; i < 4; i++) {
                obA[(size_t)(ybase + i) * HH + px] = 0.0f;
                obB[(size_t)(ybase + i) * HH + px] = 0.0f;
            }
            return;
        }
    }

    // Per-angle window metadata from tile-corner extremes (-1 floor guard),
    // with the angle's smem slot folded into the offset.
    if (tid < AA) {
        float cs = g_cs[tid];
        float ns = g_ns[tid];
        float mn = fminf(ux_lo * cs, ux_hi * cs)
                 + fminf(uy_lo * ns, uy_hi * ns) + 511.5f;
        float jminf = floorf(mn) - 1.0f;
        float off   = 511.5f - jminf + (float)((tid % CH) * WIN);
        s_meta[tid] = make_float4(cs, ns, off, 0.0f);
        s_jmin[tid] = (int)jminf;
    }

    // Warp early-out using NEAREST pixel of each lane's 4-row strip.
    float uy2min = (uy[0] * uy[3] <= 0.0f)
                 ? 0.0f
                 : fminf(uy[0] * uy[0], uy[3] * uy[3]);
    const bool active = !__all_sync(0xFFFFFFFFu, ux * ux + uy2min > 1.0f);

    float accA[4] = {0.0f, 0.0f, 0.0f, 0.0f};
    float accB[4] = {0.0f, 0.0f, 0.0f, 0.0f};
    const __half2* __restrict__ wvb = g_wv + (size_t)bp * AA * ROWP;
    const __half2* __restrict__ wdb = g_wd + (size_t)bp * AA * ROWP;

    for (int ch = 0; ch < NCH; ch++) {
        const int abase = ch * CH;
        __syncthreads();   // meta ready / previous chunk consumed
        for (int idx = tid; idx < CH * WIN; idx += 256) {
            int slot = idx / WIN;
            int k    = idx - slot * WIN;
            int a    = abase + slot;
            int src  = s_jmin[a] + 1 + k;
            src = min(max(src, 0), 1025);
            size_t g = (size_t)a * ROWP + src;
            s_w[idx]            = wvb[g];
            s_w[idx + CH * WIN] = wdb[g];
        }
        __syncthreads();

        if (active) {
            #pragma unroll 4
            for (int slot = 0; slot < CH; slot++) {
                float4 m = s_meta[abase + slot];
                float base = fmaf(ux, m.x, m.z);     // window coord incl. slot
                #pragma unroll
                for (int i = 0; i < 4; i++) {
                    float kf  = fmaf(uy[i], m.y, base);
                    int   k   = __float2int_rd(kf);          // in [0, CH*WIN)
                    float fy  = kf - (float)k;
                    __half2 fy2 = __float2half2_rn(fy);
                    __half2 v2  = s_w[k];
                    __half2 d2  = s_w[k + CH * WIN];
                    __half2 r   = __hfma2(fy2, d2, v2);      // both batches at once
                    accA[i] += __low2float(r);
                    accB[i] += __high2float(r);
                }
            }
        }
    }

    const float scale = (float)(3.14159265358979323846 / 360.0);  // pi / (2*A)
    #pragma unroll
    for (int i = 0; i < 4; i++) {
        float r2 = fmaf(uy[i], uy[i], ux * ux);
        bool  in = (r2 <= 1.0f);
        obA[(size_t)(ybase + i) * HH + px] = in ? accA[i] * scale : 0.0f;
        obB[(size_t)(ybase + i) * HH + px] = in ? accB[i] * scale : 0.0f;
    }
}

// ---------------------------------------------------------------------------
extern "C" void kernel_launch(void* const* d_in, const int* in_sizes, int n_in,
                              void* d_out, int out_size) {
    const float* x = (const float*)d_in[0];
    float* out = (float*)d_out;

    filter_kernel<<<dim3(AA, BB), 256>>>(x);
    backproject_kernel<<<dim3(HH / 32, HH / 32, NBP), dim3(32, 8)>>>(out);
}

// round 7
// speedup vs baseline: 7.5595x; 1.3187x over previous
#include <cuda_runtime.h>
#include <cuda_fp16.h>
#include <math.h>

#define HH 1024      // detector size / image size
#define AA 180       // number of angles
#define BB 16        // batch
#define NBQ (BB / 4) // batch quads

#define ROWP 1028    // uint4 entries per padded row (valid src 0..1025)
#define MTAP 128     // filter taps: m < MTAP, i.e. |d| <= 255 (tail ~5e-5 rel)

// Interleaved fp16 window entries, one uint4 = [v01, d01, v23, d23] per
// detector position j, 4 batches per entry:
//   v01 = half2( v_b0[j-1], v_b1[j-1] ),  d01 = half2( dv_b0[j], dv_b1[j] )
//   v23/d23 same for batches 2,3;  dv[j] = v[j]-v[j-1];  v[-1]=v[1024]=0.
// Bilinear pair (v[j0], v[j0+1]) lives at j = j0+1.
__device__ uint4 g_w4[NBQ * AA * ROWP];
// Pre-scaled trig: g_cs[a] = 512*cos(theta_a), g_ns[a] = -512*sin(theta_a)
__device__ float g_cs[AA];
__device__ float g_ns[AA];

// ---------------------------------------------------------------------------
// Kernel 1: angle-resample + truncated ramp-filter convolution (equivalent to
// the reference's wrap-free padded-FFT filtering; taps beyond |d|=255 dropped,
// tail ~5e-5 relative). Writes its batch's halves into the uint4 layout.
// One block per (angle, batch) column. 256 threads, 4 outputs each.
// ---------------------------------------------------------------------------
__global__ __launch_bounds__(256) void filter_kernel(const float* __restrict__ x) {
    const int a   = blockIdx.x;
    const int b   = blockIdx.y;
    const int tid = threadIdx.x;

    if (b == 0 && tid == 0) {
        float tf = (float)a * 0.017453292519943295f;   // reference f32 angle
        double t = (double)tf;
        g_cs[a] = (float)cos(t) * 512.0f;
        g_ns[a] = (float)(-sin(t)) * 512.0f;
    }

    __shared__ float sh[3 * HH];   // [0,1024) pad/reuse | [1024,2048) data | [2048,3072) pad
    __shared__ float coef[MTAP];   // coef[m] = -2 / (pi*(2m+1))^2

    for (int i = tid; i < HH; i += 256) {
        sh[i] = 0.0f;
        sh[2 * HH + i] = 0.0f;
    }
    if (tid < MTAP) {
        float d  = 2.0f * (float)tid + 1.0f;
        float pd = 3.14159265358979323846f * d;
        coef[tid] = -2.0f / (pd * pd);
    }

    // angle interpolation weights (commute with the linear filter)
    float ix = (float)a * (float)(180.0 / 179.0) - 0.5f;
    float fl = floorf(ix);
    int   i0 = (int)fl;
    float fx = ix - fl;
    int   i1 = i0 + 1;
    float w0 = (i0 >= 0 && i0 < AA) ? (1.0f - fx) : 0.0f;
    float w1 = (i1 >= 0 && i1 < AA) ? fx : 0.0f;
    int   c0 = min(max(i0, 0), AA - 1);
    int   c1 = min(max(i1, 0), AA - 1);

    const float* xb = x + (size_t)b * HH * AA;
    for (int k = tid; k < HH; k += 256) {
        sh[HH + k] = w0 * xb[k * AA + c0] + w1 * xb[k * AA + c1];
    }
    __syncthreads();

    const int h0 = tid;
    const int p0 = HH + h0;
    float acc0 = 0.5f * sh[p0];
    float acc1 = 0.5f * sh[p0 + 256];
    float acc2 = 0.5f * sh[p0 + 512];
    float acc3 = 0.5f * sh[p0 + 768];

    #pragma unroll 8
    for (int m = 0; m < MTAP; m++) {
        int   d = 2 * m + 1;
        float c = coef[m];
        acc0 = fmaf(c, sh[p0 - d]       + sh[p0 + d],       acc0);
        acc1 = fmaf(c, sh[p0 + 256 - d] + sh[p0 + 256 + d], acc1);
        acc2 = fmaf(c, sh[p0 + 512 - d] + sh[p0 + 512 + d], acc2);
        acc3 = fmaf(c, sh[p0 + 768 - d] + sh[p0 + 768 + d], acc3);
    }
    __syncthreads();                 // done reading sh before reuse

    // stash filtered column v[0..1023] into sh[0..1024)
    sh[h0]       = acc0;
    sh[h0 + 256] = acc1;
    sh[h0 + 512] = acc2;
    sh[h0 + 768] = acc3;
    __syncthreads();

    // Scatter this batch's halves into the uint4 entries.
    const size_t rowoff = ((size_t)(b >> 2) * AA + a) * ROWP;
    __half* wb = (__half*)(g_w4 + rowoff);      // 8 halves per entry
    const int sub = b & 3;
    const int g   = ((sub >> 1) << 2) | (sub & 1);   // v half-slot in entry

    #pragma unroll
    for (int i = 0; i < 4; i++) {
        int   h  = h0 + i * 256;
        float vh = sh[h];
        float vp = (h > 0) ? sh[h - 1] : 0.0f;
        wb[8 * (h + 1) + g]     = __float2half_rn(vh);        // v at j=h+1
        wb[8 * h + g + 2]       = __float2half_rn(vh - vp);   // d at j=h
    }
    if (tid == 0) {
        wb[g]                   = __float2half_rn(0.0f);        // v at j=0 (=v[-1])
        wb[8 * 1024 + g + 2]    = __float2half_rn(-sh[1023]);   // d at j=1024
        wb[8 * 1025 + g]        = __float2half_rn(0.0f);        // v at j=1025
        wb[8 * 1025 + g + 2]    = __float2half_rn(0.0f);        // d at j=1025
    }
}

// ---------------------------------------------------------------------------
// Kernel 2: backprojection, 4 batches per block (shared geometry), fp16
// interleaved (v,d) uint4 windows -> one LDS.128 per 4 samples.
// Block = 32x8 = 32x32 pixel tile, 4 y-rows and 4 batches per thread.
// Window bounds from tile-corner extremes -> every in-tile sample maps to
// k in [0, WIN-2]; no per-sample clamp.
// ---------------------------------------------------------------------------
#define CH  20                 // angles per chunk (180 = 9 * 20)
#define NCH (AA / CH)
#define WIN 48                 // window entries per angle (44 span + guards)

__global__ __launch_bounds__(256) void backproject_kernel(float* __restrict__ out) {
    __shared__ float4 s_meta[AA];          // cs, ns, off(=511.5-jminf+slot*WIN), 0
    __shared__ int    s_jmin[AA];
    __shared__ uint4  s_w[CH * WIN];       // interleaved windows (15.36 KB)

    const int tid = threadIdx.y * 32 + threadIdx.x;
    const int bq  = blockIdx.z;
    const int x0  = blockIdx.x * 32;
    const int y0  = blockIdx.y * 32;

    const float step = 2.0f / 1023.0f;
    const float ux_lo = fmaf((float)x0,        step, -1.0f);
    const float ux_hi = fmaf((float)(x0 + 31), step, -1.0f);
    const float uy_lo = fmaf((float)y0,        step, -1.0f);
    const float uy_hi = fmaf((float)(y0 + 31), step, -1.0f);

    const int px    = x0 + threadIdx.x;
    const int ybase = y0 + threadIdx.y * 4;
    float* ob0 = out + (size_t)(4 * bq) * HH * HH;
    float* ob1 = ob0 + (size_t)HH * HH;
    float* ob2 = ob1 + (size_t)HH * HH;
    float* ob3 = ob2 + (size_t)HH * HH;

    const float ux = fmaf((float)px, step, -1.0f);
    float uy[4];
    #pragma unroll
    for (int i = 0; i < 4; i++) uy[i] = fmaf((float)(ybase + i), step, -1.0f);

    // Block-level skip: nearest tile point outside unit circle.
    {
        float nx = (ux_lo > 0.0f) ? ux_lo : ((ux_hi < 0.0f) ? ux_hi : 0.0f);
        float ny = (uy_lo > 0.0f) ? uy_lo : ((uy_hi < 0.0f) ? uy_hi : 0.0f);
        if (nx * nx + ny * ny > 1.0f) {
            #pragma unroll
            for (int i = 0; i < 4; i++) {
                size_t o = (size_t)(ybase + i) * HH + px;
                ob0[o] = 0.0f; ob1[o] = 0.0f; ob2[o] = 0.0f; ob3[o] = 0.0f;
            }
            return;
        }
    }

    // Per-angle window metadata from tile-corner extremes (-1 floor guard),
    // with the angle's smem slot folded into the offset.
    if (tid < AA) {
        float cs = g_cs[tid];
        float ns = g_ns[tid];
        float mn = fminf(ux_lo * cs, ux_hi * cs)
                 + fminf(uy_lo * ns, uy_hi * ns) + 511.5f;
        float jminf = floorf(mn) - 1.0f;
        float off   = 511.5f - jminf + (float)((tid % CH) * WIN);
        s_meta[tid] = make_float4(cs, ns, off, 0.0f);
        s_jmin[tid] = (int)jminf;
    }

    // Warp early-out using NEAREST pixel of each lane's 4-row strip.
    float uy2min = (uy[0] * uy[3] <= 0.0f)
                 ? 0.0f
                 : fminf(uy[0] * uy[0], uy[3] * uy[3]);
    const bool active = !__all_sync(0xFFFFFFFFu, ux * ux + uy2min > 1.0f);

    float a0[4] = {0,0,0,0}, a1[4] = {0,0,0,0};
    float a2[4] = {0,0,0,0}, a3[4] = {0,0,0,0};
    const uint4* __restrict__ wq = g_w4 + (size_t)bq * AA * ROWP;

    for (int ch = 0; ch < NCH; ch++) {
        const int abase = ch * CH;
        __syncthreads();   // meta ready / previous chunk consumed
        for (int idx = tid; idx < CH * WIN; idx += 256) {
            int slot = idx / WIN;
            int k    = idx - slot * WIN;
            int a    = abase + slot;
            int src  = s_jmin[a] + 1 + k;
            src = min(max(src, 0), 1025);
            s_w[idx] = wq[(size_t)a * ROWP + src];
        }
        __syncthreads();

        if (active) {
            #pragma unroll 4
            for (int slot = 0; slot < CH; slot++) {
                float4 m = s_meta[abase + slot];
                float base = fmaf(ux, m.x, m.z);     // window coord incl. slot
                #pragma unroll
                for (int i = 0; i < 4; i++) {
                    float kf  = fmaf(uy[i], m.y, base);
                    int   k   = __float2int_rd(kf);          // in [0, CH*WIN)
                    float fy  = kf - (float)k;
                    __half2 fy2 = __float2half2_rn(fy);
                    uint4 w = s_w[k];                        // one LDS.128
                    __half2 v01 = *reinterpret_cast<__half2*>(&w.x);
                    __half2 d01 = *reinterpret_cast<__half2*>(&w.y);
                    __half2 v23 = *reinterpret_cast<__half2*>(&w.z);
                    __half2 d23 = *reinterpret_cast<__half2*>(&w.w);
                    __half2 r01 = __hfma2(fy2, d01, v01);
                    __half2 r23 = __hfma2(fy2, d23, v23);
                    a0[i] += __low2float(r01);
                    a1[i] += __high2float(r01);
                    a2[i] += __low2float(r23);
                    a3[i] += __high2float(r23);
                }
            }
        }
    }

    const float scale = (float)(3.14159265358979323846 / 360.0);  // pi / (2*A)
    #pragma unroll
    for (int i = 0; i < 4; i++) {
        float r2 = fmaf(uy[i], uy[i], ux * ux);
        bool  in = (r2 <= 1.0f);
        size_t o = (size_t)(ybase + i) * HH + px;
        ob0[o] = in ? a0[i] * scale : 0.0f;
        ob1[o] = in ? a1[i] * scale : 0.0f;
        ob2[o] = in ? a2[i] * scale : 0.0f;
        ob3[o] = in ? a3[i] * scale : 0.0f;
    }
}

// ---------------------------------------------------------------------------
extern "C" void kernel_launch(void* const* d_in, const int* in_sizes, int n_in,
                              void* d_out, int out_size) {
    const float* x = (const float*)d_in[0];
    float* out = (float*)d_out;

    filter_kernel<<<dim3(AA, BB), 256>>>(x);
    backproject_kernel<<<dim3(HH / 32, HH / 32, NBQ), dim3(32, 8)>>>(out);
}

// round 8
// speedup vs baseline: 8.8903x; 1.1760x over previous
#include <cuda_runtime.h>
#include <cuda_fp16.h>
#include <math.h>

#define HH 1024      // detector size / image size
#define AA 180       // number of angles
#define BB 16        // batch
#define NBQ (BB / 4) // batch quads
#define NBO (BB / 8) // batch octets

#define ROWP 1028    // uint4 entries per padded row (valid src 0..1025)
#define MTAP 64      // filter taps: m < MTAP, i.e. |d| <= 127 (tail ~1.3e-4 rel)

// Interleaved fp16 window entries, one uint4 = [v01, d01, v23, d23] per
// detector position j, 4 batches per entry:
//   v01 = half2( v_b0[j-1], v_b1[j-1] ),  d01 = half2( dv_b0[j], dv_b1[j] )
//   v23/d23 same for batches 2,3;  dv[j] = v[j]-v[j-1];  v[-1]=v[1024]=0.
// Bilinear pair (v[j0], v[j0+1]) lives at j = j0+1.
__device__ uint4 g_w4[NBQ * AA * ROWP];
// Pre-scaled trig: g_cs[a] = 512*cos(theta_a), g_ns[a] = -512*sin(theta_a)
__device__ float g_cs[AA];
__device__ float g_ns[AA];

// ---------------------------------------------------------------------------
// Kernel 1: angle-resample + truncated ramp-filter convolution (equivalent to
// the reference's wrap-free padded-FFT filtering; taps beyond |d|=127 dropped,
// tail ~1.3e-4 relative, well under the fp16 window quantization). Writes its
// batch's halves into the uint4 layout.
// One block per (angle, batch) column. 256 threads, 4 outputs each.
// ---------------------------------------------------------------------------
__global__ __launch_bounds__(256) void filter_kernel(const float* __restrict__ x) {
    const int a   = blockIdx.x;
    const int b   = blockIdx.y;
    const int tid = threadIdx.x;

    if (b == 0 && tid == 0) {
        float tf = (float)a * 0.017453292519943295f;   // reference f32 angle
        double t = (double)tf;
        g_cs[a] = (float)cos(t) * 512.0f;
        g_ns[a] = (float)(-sin(t)) * 512.0f;
    }

    __shared__ float sh[3 * HH];   // [0,1024) pad/reuse | [1024,2048) data | [2048,3072) pad
    __shared__ float coef[MTAP];   // coef[m] = -2 / (pi*(2m+1))^2

    for (int i = tid; i < HH; i += 256) {
        sh[i] = 0.0f;
        sh[2 * HH + i] = 0.0f;
    }
    if (tid < MTAP) {
        float d  = 2.0f * (float)tid + 1.0f;
        float pd = 3.14159265358979323846f * d;
        coef[tid] = -2.0f / (pd * pd);
    }

    // angle interpolation weights (commute with the linear filter)
    float ix = (float)a * (float)(180.0 / 179.0) - 0.5f;
    float fl = floorf(ix);
    int   i0 = (int)fl;
    float fx = ix - fl;
    int   i1 = i0 + 1;
    float w0 = (i0 >= 0 && i0 < AA) ? (1.0f - fx) : 0.0f;
    float w1 = (i1 >= 0 && i1 < AA) ? fx : 0.0f;
    int   c0 = min(max(i0, 0), AA - 1);
    int   c1 = min(max(i1, 0), AA - 1);

    const float* xb = x + (size_t)b * HH * AA;
    for (int k = tid; k < HH; k += 256) {
        sh[HH + k] = w0 * xb[k * AA + c0] + w1 * xb[k * AA + c1];
    }
    __syncthreads();

    const int h0 = tid;
    const int p0 = HH + h0;
    float acc0 = 0.5f * sh[p0];
    float acc1 = 0.5f * sh[p0 + 256];
    float acc2 = 0.5f * sh[p0 + 512];
    float acc3 = 0.5f * sh[p0 + 768];

    #pragma unroll 8
    for (int m = 0; m < MTAP; m++) {
        int   d = 2 * m + 1;
        float c = coef[m];
        acc0 = fmaf(c, sh[p0 - d]       + sh[p0 + d],       acc0);
        acc1 = fmaf(c, sh[p0 + 256 - d] + sh[p0 + 256 + d], acc1);
        acc2 = fmaf(c, sh[p0 + 512 - d] + sh[p0 + 512 + d], acc2);
        acc3 = fmaf(c, sh[p0 + 768 - d] + sh[p0 + 768 + d], acc3);
    }
    __syncthreads();                 // done reading sh before reuse

    // stash filtered column v[0..1023] into sh[0..1024)
    sh[h0]       = acc0;
    sh[h0 + 256] = acc1;
    sh[h0 + 512] = acc2;
    sh[h0 + 768] = acc3;
    __syncthreads();

    // Scatter this batch's halves into the uint4 entries.
    const size_t rowoff = ((size_t)(b >> 2) * AA + a) * ROWP;
    __half* wb = (__half*)(g_w4 + rowoff);      // 8 halves per entry
    const int sub = b & 3;
    const int g   = ((sub >> 1) << 2) | (sub & 1);   // v half-slot in entry

    #pragma unroll
    for (int i = 0; i < 4; i++) {
        int   h  = h0 + i * 256;
        float vh = sh[h];
        float vp = (h > 0) ? sh[h - 1] : 0.0f;
        wb[8 * (h + 1) + g]     = __float2half_rn(vh);        // v at j=h+1
        wb[8 * h + g + 2]       = __float2half_rn(vh - vp);   // d at j=h
    }
    if (tid == 0) {
        wb[g]                   = __float2half_rn(0.0f);        // v at j=0 (=v[-1])
        wb[8 * 1024 + g + 2]    = __float2half_rn(-sh[1023]);   // d at j=1024
        wb[8 * 1025 + g]        = __float2half_rn(0.0f);        // v at j=1025
        wb[8 * 1025 + g + 2]    = __float2half_rn(0.0f);        // d at j=1025
    }
}

// ---------------------------------------------------------------------------
// Kernel 2: backprojection, 8 batches per block (shared geometry), fp16
// interleaved (v,d) uint4 windows -> two LDS.128 per 8 samples, one shared
// index computation. Block = 32x8 = 32x32 pixel tile, 4 y-rows and 8 batches
// per thread. Window bounds from tile-corner extremes -> every in-tile
// sample maps to k in [0, WIN-2]; no per-sample clamp.
// ---------------------------------------------------------------------------
#define CH  12                 // angles per chunk (180 = 15 * 12)
#define NCH (AA / CH)
#define WIN 48                 // window entries per angle (44 span + guards)

__global__ __launch_bounds__(256) void backproject_kernel(float* __restrict__ out) {
    __shared__ float4 s_meta[AA];          // cs, ns, off(=511.5-jminf+slot*WIN), 0
    __shared__ int    s_jmin[AA];
    __shared__ uint4  s_w[2 * CH * WIN];   // plane0: batches 0-3, plane1: 4-7

    const int tid = threadIdx.y * 32 + threadIdx.x;
    const int bo  = blockIdx.z;            // batch octet
    const int x0  = blockIdx.x * 32;
    const int y0  = blockIdx.y * 32;

    const float step = 2.0f / 1023.0f;
    const float ux_lo = fmaf((float)x0,        step, -1.0f);
    const float ux_hi = fmaf((float)(x0 + 31), step, -1.0f);
    const float uy_lo = fmaf((float)y0,        step, -1.0f);
    const float uy_hi = fmaf((float)(y0 + 31), step, -1.0f);

    const int px    = x0 + threadIdx.x;
    const int ybase = y0 + threadIdx.y * 4;
    float* ob = out + (size_t)(8 * bo) * HH * HH;

    const float ux = fmaf((float)px, step, -1.0f);
    float uy[4];
    #pragma unroll
    for (int i = 0; i < 4; i++) uy[i] = fmaf((float)(ybase + i), step, -1.0f);

    // Block-level skip: nearest tile point outside unit circle.
    {
        float nx = (ux_lo > 0.0f) ? ux_lo : ((ux_hi < 0.0f) ? ux_hi : 0.0f);
        float ny = (uy_lo > 0.0f) ? uy_lo : ((uy_hi < 0.0f) ? uy_hi : 0.0f);
        if (nx * nx + ny * ny > 1.0f) {
            #pragma unroll
            for (int i = 0; i < 4; i++) {
                size_t o = (size_t)(ybase + i) * HH + px;
                #pragma unroll
                for (int q = 0; q < 8; q++)
                    ob[(size_t)q * HH * HH + o] = 0.0f;
            }
            return;
        }
    }

    // Per-angle window metadata from tile-corner extremes (-1 floor guard),
    // with the angle's smem slot folded into the offset.
    if (tid < AA) {
        float cs = g_cs[tid];
        float ns = g_ns[tid];
        float mn = fminf(ux_lo * cs, ux_hi * cs)
                 + fminf(uy_lo * ns, uy_hi * ns) + 511.5f;
        float jminf = floorf(mn) - 1.0f;
        float off   = 511.5f - jminf + (float)((tid % CH) * WIN);
        s_meta[tid] = make_float4(cs, ns, off, 0.0f);
        s_jmin[tid] = (int)jminf;
    }

    // Warp early-out using NEAREST pixel of each lane's 4-row strip.
    float uy2min = (uy[0] * uy[3] <= 0.0f)
                 ? 0.0f
                 : fminf(uy[0] * uy[0], uy[3] * uy[3]);
    const bool active = !__all_sync(0xFFFFFFFFu, ux * ux + uy2min > 1.0f);

    float acc[8][4];
    #pragma unroll
    for (int q = 0; q < 8; q++)
        #pragma unroll
        for (int i = 0; i < 4; i++) acc[q][i] = 0.0f;

    const uint4* __restrict__ wqA = g_w4 + (size_t)(2 * bo)     * AA * ROWP;
    const uint4* __restrict__ wqB = g_w4 + (size_t)(2 * bo + 1) * AA * ROWP;

    for (int ch = 0; ch < NCH; ch++) {
        const int abase = ch * CH;
        __syncthreads();   // meta ready / previous chunk consumed
        for (int idx = tid; idx < CH * WIN; idx += 256) {
            int slot = idx / WIN;
            int k    = idx - slot * WIN;
            int a    = abase + slot;
            int src  = s_jmin[a] + 1 + k;
            src = min(max(src, 0), 1025);
            size_t g = (size_t)a * ROWP + src;
            s_w[idx]            = wqA[g];
            s_w[idx + CH * WIN] = wqB[g];
        }
        __syncthreads();

        if (active) {
            #pragma unroll 4
            for (int slot = 0; slot < CH; slot++) {
                float4 m = s_meta[abase + slot];
                float base = fmaf(ux, m.x, m.z);     // window coord incl. slot
                #pragma unroll
                for (int i = 0; i < 4; i++) {
                    float kf  = fmaf(uy[i], m.y, base);
                    int   k   = __float2int_rd(kf);          // in [0, CH*WIN)
                    float fy  = kf - (float)k;
                    __half2 fy2 = __float2half2_rn(fy);
                    uint4 wA = s_w[k];                       // LDS.128, batches 0-3
                    uint4 wB = s_w[k + CH * WIN];            // LDS.128, batches 4-7
                    __half2 rA0 = __hfma2(fy2, *reinterpret_cast<__half2*>(&wA.y),
                                               *reinterpret_cast<__half2*>(&wA.x));
                    __half2 rA1 = __hfma2(fy2, *reinterpret_cast<__half2*>(&wA.w),
                                               *reinterpret_cast<__half2*>(&wA.z));
                    __half2 rB0 = __hfma2(fy2, *reinterpret_cast<__half2*>(&wB.y),
                                               *reinterpret_cast<__half2*>(&wB.x));
                    __half2 rB1 = __hfma2(fy2, *reinterpret_cast<__half2*>(&wB.w),
                                               *reinterpret_cast<__half2*>(&wB.z));
                    acc[0][i] += __low2float(rA0);
                    acc[1][i] += __high2float(rA0);
                    acc[2][i] += __low2float(rA1);
                    acc[3][i] += __high2float(rA1);
                    acc[4][i] += __low2float(rB0);
                    acc[5][i] += __high2float(rB0);
                    acc[6][i] += __low2float(rB1);
                    acc[7][i] += __high2float(rB1);
                }
            }
        }
    }

    const float scale = (float)(3.14159265358979323846 / 360.0);  // pi / (2*A)
    #pragma unroll
    for (int i = 0; i < 4; i++) {
        float r2 = fmaf(uy[i], uy[i], ux * ux);
        bool  in = (r2 <= 1.0f);
        size_t o = (size_t)(ybase + i) * HH + px;
        #pragma unroll
        for (int q = 0; q < 8; q++)
            ob[(size_t)q * HH * HH + o] = in ? acc[q][i] * scale : 0.0f;
    }
}

// ---------------------------------------------------------------------------
extern "C" void kernel_launch(void* const* d_in, const int* in_sizes, int n_in,
                              void* d_out, int out_size) {
    const float* x = (const float*)d_in[0];
    float* out = (float*)d_out;

    filter_kernel<<<dim3(AA, BB), 256>>>(x);
    backproject_kernel<<<dim3(HH / 32, HH / 32, NBO), dim3(32, 8)>>>(out);
}